// round 14
// baseline (speedup 1.0000x reference)
#include <cuda_runtime.h>
#include <cstdint>

#define BB 4
#define QQ 1024
#define KKEYS 2048
#define NB 16
#define VD 512
#define CHUNK 256
#define ROWS 8            // rows per K1 block: 4 packed row-pairs
#define NCH 4             // chunks per K1 block (key-split: 1024 keys)
#define NROWS (BB * QQ)
#define CAPG 256
#define TAU 2e-7f

typedef unsigned long long ull;
#define SGN2   0x8000000080000000ULL
#define ONES2  0x3F8000003F800000ULL
#define SC2    0x4380000043800000ULL   // (256.0f, 256.0f) exact 2^8 scale

static __device__ __forceinline__ ull pk2(float a, float b) {
    ull r; asm("mov.b64 %0,{%1,%2};" : "=l"(r) : "f"(a), "f"(b)); return r;
}
static __device__ __forceinline__ void upk2(ull v, float& a, float& b) {
    asm("mov.b64 {%0,%1},%2;" : "=f"(a), "=f"(b) : "l"(v));
}
static __device__ __forceinline__ ull add2(ull a, ull b) {
    ull r; asm("add.rn.f32x2 %0,%1,%2;" : "=l"(r) : "l"(a), "l"(b)); return r;
}
static __device__ __forceinline__ ull mul2(ull a, ull b) {
    ull r; asm("mul.rn.f32x2 %0,%1,%2;" : "=l"(r) : "l"(a), "l"(b)); return r;
}

// Global scratch (device globals: the sanctioned no-alloc path).
__device__ float g_sum[NROWS];
__device__ int   g_cnt[NROWS];
__device__ float g_w[NROWS * CAPG];
__device__ int   g_idx[NROWS * CAPG];

// ---------------------------------------------------------------------------
// K0: zero per-row sum + count (determinism across graph replays).
// ---------------------------------------------------------------------------
__global__ void init_kernel()
{
    int i = blockIdx.x * 256 + threadIdx.x;
    if (i < NROWS) { g_sum[i] = 0.0f; g_cnt[i] = 0; }
}

// ---------------------------------------------------------------------------
// K1: producer. Block = 8 rows x 1024 keys; grid 1024. Writes raw
// r10 = (256 p)^10 into W and accumulates per-row partial sums into g_sum.
// ---------------------------------------------------------------------------
__global__ void __launch_bounds__(256, 4) prod10_kernel(
    const float* __restrict__ qbits,
    const float* __restrict__ kbits,
    const int*   __restrict__ mask,
    float*       __restrict__ W)
{
    __shared__ float skey[CHUNK * 20];     // pad 20 -> conflict-free LDS.128
    __shared__ int   smask[CHUNK];
    __shared__ ull   sqn[4][NB];           // packed negated q bits per pair

    const int tid = threadIdx.x;
    const int w   = tid >> 5;              // warp 0..7
    const int kx  = tid & 31;
    const int p   = w >> 1;                // row-pair 0..3
    const int h   = w & 1;                 // key half within chunk
    const int bid = blockIdx.x;
    const int kh  = bid & 1;               // key half of the row
    const int qt  = (bid >> 1) & 127;
    const int b   = bid >> 8;
    const int rowbase = b * QQ + qt * ROWS;
    const int rowA = rowbase + 2 * p;
    const int rowB = rowA + 1;

    if (tid < 4 * NB) {                    // packed negated query bits
        int pp = tid >> 4, bit = tid & 15;
        int rA = rowbase + 2 * pp;
        float qa = qbits[(size_t)rA * NB + bit];
        float qc = qbits[(size_t)(rA + 1) * NB + bit];
        sqn[pp][bit] = pk2(-qa, -qc);
    }

    float* wrA = W + (size_t)rowA * KKEYS;
    float* wrB = W + (size_t)rowB * KKEYS;
    const float4* kbase4 = (const float4*)(kbits + (size_t)b * KKEYS * NB);
    const int*    mbase  = mask + b * KKEYS;

    ull s2 = 0ULL;                         // packed partial sums (rowA,rowB)
    for (int c = 0; c < NCH; c++) {
        const int cg = kh * NCH + c;       // global chunk 0..7
#pragma unroll
        for (int it = 0; it < 4; it++) {   // stage 256 keys x 16 floats
            int i = tid + it * 256;
            int k = i >> 2, j = i & 3;
            float4 v = kbase4[(size_t)(cg * CHUNK + k) * 4 + j];
            *(float4*)&skey[k * 20 + j * 4] = v;
        }
        if (tid < CHUNK) smask[tid] = mbase[cg * CHUNK + tid];
        __syncthreads();

        ull prod[4];
#pragma unroll 1
        for (int g = 0; g < 4; g++) {      // bit-group outer: few live q-regs
            const ull q0 = sqn[p][g * 4 + 0];
            const ull q1 = sqn[p][g * 4 + 1];
            const ull q2 = sqn[p][g * 4 + 2];
            const ull q3 = sqn[p][g * 4 + 3];
#pragma unroll
            for (int j = 0; j < 4; j++) {
                const int kl = h * 128 + j * 32 + kx;
                float4 kv = *(const float4*)&skey[kl * 20 + g * 4];
                // t = 1 - |q-k| = 1 + ((k-q) | signbit)
                ull t0 = add2(ONES2, add2(q0, pk2(kv.x, kv.x)) | SGN2);
                ull t1 = add2(ONES2, add2(q1, pk2(kv.y, kv.y)) | SGN2);
                ull t2 = add2(ONES2, add2(q2, pk2(kv.z, kv.z)) | SGN2);
                ull t3 = add2(ONES2, add2(q3, pk2(kv.w, kv.w)) | SGN2);
                ull m  = mul2(mul2(t0, t1), mul2(t2, t3));
                prod[j] = (g == 0) ? m : mul2(prod[j], m);
            }
        }
#pragma unroll
        for (int j = 0; j < 4; j++) {
            const int kl = h * 128 + j * 32 + kx;
            // r10 = (256*p)^10  (exact 2^80 scale; max-free normalization)
            ull r   = mul2(prod[j], SC2);
            ull r2  = mul2(r, r);
            ull r4  = mul2(r2, r2);
            ull r8  = mul2(r4, r4);
            ull r10 = mul2(r8, r2);
            float ra, rb; upk2(r10, ra, rb);
            if (smask[kl] == 0) { ra = 0.0f; rb = 0.0f; }
            const int kg = cg * CHUNK + kl;
            wrA[kg] = ra;
            wrB[kg] = rb;
            s2 = add2(s2, pk2(ra, rb));
        }
        __syncthreads();
    }

    // per-row partial sums -> global
    float sA, sB; upk2(s2, sA, sB);
#pragma unroll
    for (int off = 16; off; off >>= 1) {
        sA += __shfl_xor_sync(0xffffffffu, sA, off);
        sB += __shfl_xor_sync(0xffffffffu, sB, off);
    }
    if (kx == 0) {
        atomicAdd(&g_sum[rowA], sA);
        atomicAdd(&g_sum[rowB], sB);
    }
}

// ---------------------------------------------------------------------------
// K2a: barrier-free streaming normalize + compact. One float4 per thread.
// ---------------------------------------------------------------------------
__global__ void __launch_bounds__(256, 8) norm_kernel(float* __restrict__ W)
{
    const int gid = blockIdx.x * 256 + threadIdx.x;   // float4 index
    const int row = gid >> 9;                         // 512 float4 per row
    const float invs = 1.0f / g_sum[row];

    float4* w4 = (float4*)W + gid;
    float4 v = *w4;
    v.x *= invs; v.y *= invs; v.z *= invs; v.w *= invs;
    *w4 = v;

    const int k0 = (gid & 511) * 4;                   // local key index
    float e[4] = {v.x, v.y, v.z, v.w};
#pragma unroll
    for (int q = 0; q < 4; q++) {
        if (e[q] > TAU) {
            int pos = atomicAdd(&g_cnt[row], 1);
            if (pos < CAPG) {
                g_w[row * CAPG + pos]   = e[q];
                g_idx[row * CAPG + pos] = k0 + q;
            }
        }
    }
}

// ---------------------------------------------------------------------------
// K2b: gather-only sparse GEMV. Block per row; never reads W (sparse path).
// ---------------------------------------------------------------------------
__global__ void __launch_bounds__(256, 8) gemv_kernel(
    const float* __restrict__ W,
    const float* __restrict__ vals,
    float*       __restrict__ Out)
{
    __shared__ float sw[CAPG];
    __shared__ int   sidx[CAPG];

    const int row = blockIdx.x;
    const int b   = row >> 10;
    const int tid = threadIdx.x;
    const int S   = g_cnt[row];
    const float* V = vals + (size_t)b * KKEYS * VD;

    float ax = 0.0f, ay = 0.0f;
    if (S <= CAPG) {
        if (tid < S) {
            sw[tid]   = g_w[row * CAPG + tid];
            sidx[tid] = g_idx[row * CAPG + tid];
        }
        __syncthreads();
        for (int s = 0; s < S; s++) {
            float wgt = sw[s];
            const float2 v = ((const float2*)(V + (size_t)sidx[s] * VD))[tid];
            ax = fmaf(wgt, v.x, ax);
            ay = fmaf(wgt, v.y, ay);
        }
    } else {
        // dense fallback: W already normalized by K2a
        const float* wr = W + (size_t)row * KKEYS;
        for (int k = 0; k < KKEYS; k++) {
            float wgt = wr[k];
            if (wgt > TAU) {
                const float2 v = ((const float2*)(V + (size_t)k * VD))[tid];
                ax = fmaf(wgt, v.x, ax);
                ay = fmaf(wgt, v.y, ay);
            }
        }
    }
    ((float2*)(Out + (size_t)row * VD))[tid] = make_float2(ax, ay);
}

// ---------------------------------------------------------------------------
// Launch: out layout = [output (B,Q,V) | weights (B,Q,K)] per reference tuple.
// ---------------------------------------------------------------------------
extern "C" void kernel_launch(void* const* d_in, const int* in_sizes, int n_in,
                              void* d_out, int out_size)
{
    (void)in_sizes; (void)n_in; (void)out_size;
    const float* qb   = (const float*)d_in[0];
    const float* kb   = (const float*)d_in[1];
    const float* vals = (const float*)d_in[2];
    const int*   mask = (const int*)d_in[3];

    float* out = (float*)d_out;
    float* W   = out + (size_t)BB * QQ * VD;   // weights region

    init_kernel<<<(NROWS + 255) / 256, 256>>>();
    prod10_kernel<<<BB * (QQ / ROWS) * 2, 256>>>(qb, kb, mask, W);
    norm_kernel<<<(NROWS * KKEYS / 4) / 256, 256>>>(W);
    gemv_kernel<<<NROWS, 256>>>(W, vals, out);
}

// round 15
// speedup vs baseline: 1.2460x; 1.2460x over previous
#include <cuda_runtime.h>
#include <cstdint>

#define BB 4
#define QQ 1024
#define KKEYS 2048
#define NB 16
#define VD 512
#define CHUNK 256
#define ROWS 8            // rows per K1 block: 4 packed row-pairs
#define NCH 4             // chunks per K1 block (key-split: 1024 keys)
#define NROWS (BB * QQ)
#define CAP 256
#define TAU 2e-7f

typedef unsigned long long ull;
#define SGN2   0x8000000080000000ULL
#define ONES2  0x3F8000003F800000ULL
#define SC2    0x4380000043800000ULL   // (256.0f, 256.0f) exact 2^8 scale

static __device__ __forceinline__ ull pk2(float a, float b) {
    ull r; asm("mov.b64 %0,{%1,%2};" : "=l"(r) : "f"(a), "f"(b)); return r;
}
static __device__ __forceinline__ void upk2(ull v, float& a, float& b) {
    asm("mov.b64 {%0,%1},%2;" : "=f"(a), "=f"(b) : "l"(v));
}
static __device__ __forceinline__ ull add2(ull a, ull b) {
    ull r; asm("add.rn.f32x2 %0,%1,%2;" : "=l"(r) : "l"(a), "l"(b)); return r;
}
static __device__ __forceinline__ ull mul2(ull a, ull b) {
    ull r; asm("mul.rn.f32x2 %0,%1,%2;" : "=l"(r) : "l"(a), "l"(b)); return r;
}

// Per-row sums (device global scratch — the sanctioned no-alloc path).
__device__ float g_sum[NROWS];

// ---------------------------------------------------------------------------
// K0: zero per-row sums (determinism across graph replays).
// ---------------------------------------------------------------------------
__global__ void init_kernel()
{
    int i = blockIdx.x * 256 + threadIdx.x;
    if (i < NROWS) g_sum[i] = 0.0f;
}

// ---------------------------------------------------------------------------
// K1: producer. Block = 8 rows x 1024 keys; grid 1024. Writes raw
// r10 = (256 p)^10 into W and accumulates per-row sums into g_sum.
// ---------------------------------------------------------------------------
__global__ void __launch_bounds__(256, 4) prod10_kernel(
    const float* __restrict__ qbits,
    const float* __restrict__ kbits,
    const int*   __restrict__ mask,
    float*       __restrict__ W)
{
    __shared__ float skey[CHUNK * 20];     // pad 20 -> conflict-free LDS.128
    __shared__ int   smask[CHUNK];
    __shared__ ull   sqn[4][NB];           // packed negated q bits per pair

    const int tid = threadIdx.x;
    const int w   = tid >> 5;              // warp 0..7
    const int kx  = tid & 31;
    const int p   = w >> 1;                // row-pair 0..3
    const int h   = w & 1;                 // key half within chunk
    const int bid = blockIdx.x;
    const int kh  = bid & 1;               // key half of the row
    const int qt  = (bid >> 1) & 127;
    const int b   = bid >> 8;
    const int rowbase = b * QQ + qt * ROWS;
    const int rowA = rowbase + 2 * p;
    const int rowB = rowA + 1;

    if (tid < 4 * NB) {                    // packed negated query bits
        int pp = tid >> 4, bit = tid & 15;
        int rA = rowbase + 2 * pp;
        float qa = qbits[(size_t)rA * NB + bit];
        float qc = qbits[(size_t)(rA + 1) * NB + bit];
        sqn[pp][bit] = pk2(-qa, -qc);
    }

    float* wrA = W + (size_t)rowA * KKEYS;
    float* wrB = W + (size_t)rowB * KKEYS;
    const float4* kbase4 = (const float4*)(kbits + (size_t)b * KKEYS * NB);
    const int*    mbase  = mask + b * KKEYS;

    ull s2 = 0ULL;                         // packed partial sums (rowA,rowB)
    for (int c = 0; c < NCH; c++) {
        const int cg = kh * NCH + c;       // global chunk 0..7
#pragma unroll
        for (int it = 0; it < 4; it++) {   // stage 256 keys x 16 floats
            int i = tid + it * 256;
            int k = i >> 2, j = i & 3;
            float4 v = kbase4[(size_t)(cg * CHUNK + k) * 4 + j];
            *(float4*)&skey[k * 20 + j * 4] = v;
        }
        if (tid < CHUNK) smask[tid] = mbase[cg * CHUNK + tid];
        __syncthreads();

        ull prod[4];
#pragma unroll 1
        for (int g = 0; g < 4; g++) {      // bit-group outer: few live q-regs
            const ull q0 = sqn[p][g * 4 + 0];
            const ull q1 = sqn[p][g * 4 + 1];
            const ull q2 = sqn[p][g * 4 + 2];
            const ull q3 = sqn[p][g * 4 + 3];
#pragma unroll
            for (int j = 0; j < 4; j++) {
                const int kl = h * 128 + j * 32 + kx;
                float4 kv = *(const float4*)&skey[kl * 20 + g * 4];
                // t = 1 - |q-k| = 1 + ((k-q) | signbit)
                ull t0 = add2(ONES2, add2(q0, pk2(kv.x, kv.x)) | SGN2);
                ull t1 = add2(ONES2, add2(q1, pk2(kv.y, kv.y)) | SGN2);
                ull t2 = add2(ONES2, add2(q2, pk2(kv.z, kv.z)) | SGN2);
                ull t3 = add2(ONES2, add2(q3, pk2(kv.w, kv.w)) | SGN2);
                ull m  = mul2(mul2(t0, t1), mul2(t2, t3));
                prod[j] = (g == 0) ? m : mul2(prod[j], m);
            }
        }
#pragma unroll
        for (int j = 0; j < 4; j++) {
            const int kl = h * 128 + j * 32 + kx;
            // r10 = (256*p)^10  (exact 2^80 scale; max-free normalization)
            ull r   = mul2(prod[j], SC2);
            ull r2  = mul2(r, r);
            ull r4  = mul2(r2, r2);
            ull r8  = mul2(r4, r4);
            ull r10 = mul2(r8, r2);
            float ra, rb; upk2(r10, ra, rb);
            if (smask[kl] == 0) { ra = 0.0f; rb = 0.0f; }
            const int kg = cg * CHUNK + kl;
            wrA[kg] = ra;
            wrB[kg] = rb;
            s2 = add2(s2, pk2(ra, rb));
        }
        __syncthreads();
    }

    // per-row partial sums -> global
    float sA, sB; upk2(s2, sA, sB);
#pragma unroll
    for (int off = 16; off; off >>= 1) {
        sA += __shfl_xor_sync(0xffffffffu, sA, off);
        sB += __shfl_xor_sync(0xffffffffu, sB, off);
    }
    if (kx == 0) {
        atomicAdd(&g_sum[rowA], sA);
        atomicAdd(&g_sum[rowB], sB);
    }
}

// ---------------------------------------------------------------------------
// K2: combined consumer, one block per row (grid 4096). Uses g_sum from K1 —
// NO block reduction. Chain: issue W loads -> barrier (overlapped) ->
// normalize+store+compact -> barrier -> sparse GEMV.
// ---------------------------------------------------------------------------
__global__ void __launch_bounds__(256, 8) norm_gemv_kernel(
    float*       __restrict__ W,
    const float* __restrict__ vals,
    float*       __restrict__ Out)
{
    __shared__ float sw[CAP];
    __shared__ int   sidx[CAP];
    __shared__ int   scnt;

    const int row = blockIdx.x;
    const int b   = row >> 10;
    const int tid = threadIdx.x;
    float4* wr4 = (float4*)(W + (size_t)row * KKEYS);

    if (tid == 0) scnt = 0;

    // issue loads first: W row chunks + the row sum (latency hides under barrier)
    float4 v0 = wr4[tid];
    float4 v1 = wr4[tid + 256];
    const float invs = 1.0f / g_sum[row];
    __syncthreads();                       // scnt=0 visible

    // normalize + write back + compact (S ~ 7 -> few smem atomics)
    v0.x *= invs; v0.y *= invs; v0.z *= invs; v0.w *= invs;
    v1.x *= invs; v1.y *= invs; v1.z *= invs; v1.w *= invs;
    wr4[tid]       = v0;
    wr4[tid + 256] = v1;
    {
        float e[8] = {v0.x, v0.y, v0.z, v0.w, v1.x, v1.y, v1.z, v1.w};
#pragma unroll
        for (int q = 0; q < 8; q++) {
            if (e[q] > TAU) {
                int pos = atomicAdd(&scnt, 1);
                int k = (q < 4) ? (tid * 4 + q) : ((tid + 256) * 4 + q - 4);
                if (pos < CAP) { sw[pos] = e[q]; sidx[pos] = k; }
            }
        }
    }
    __syncthreads();

    const int S = scnt;
    const float* V = vals + (size_t)b * KKEYS * VD;
    float ax = 0.0f, ay = 0.0f;
    if (S <= CAP) {
        for (int s = 0; s < S; s++) {
            float wgt = sw[s];
            const float2 v = ((const float2*)(V + (size_t)sidx[s] * VD))[tid];
            ax = fmaf(wgt, v.x, ax);
            ay = fmaf(wgt, v.y, ay);
        }
    } else {
        // dense fallback: W row normalized above (ordered by the barrier)
        const float* wr = W + (size_t)row * KKEYS;
        for (int k = 0; k < KKEYS; k++) {
            float wgt = wr[k];
            if (wgt > TAU) {
                const float2 v = ((const float2*)(V + (size_t)k * VD))[tid];
                ax = fmaf(wgt, v.x, ax);
                ay = fmaf(wgt, v.y, ay);
            }
        }
    }
    ((float2*)(Out + (size_t)row * VD))[tid] = make_float2(ax, ay);
}

// ---------------------------------------------------------------------------
// Launch: out layout = [output (B,Q,V) | weights (B,Q,K)] per reference tuple.
// ---------------------------------------------------------------------------
extern "C" void kernel_launch(void* const* d_in, const int* in_sizes, int n_in,
                              void* d_out, int out_size)
{
    (void)in_sizes; (void)n_in; (void)out_size;
    const float* qb   = (const float*)d_in[0];
    const float* kb   = (const float*)d_in[1];
    const float* vals = (const float*)d_in[2];
    const int*   mask = (const int*)d_in[3];

    float* out = (float*)d_out;
    float* W   = out + (size_t)BB * QQ * VD;   // weights region

    init_kernel<<<(NROWS + 255) / 256, 256>>>();
    prod10_kernel<<<BB * (QQ / ROWS) * 2, 256>>>(qb, kb, mask, W);
    norm_gemv_kernel<<<NROWS, 256>>>(W, vals, out);
}

// round 16
// speedup vs baseline: 1.2637x; 1.0142x over previous
#include <cuda_runtime.h>
#include <cstdint>

#define BB 4
#define QQ 1024
#define KKEYS 2048
#define NB 16
#define VD 512
#define CHUNK 256
#define ROWS 8            // rows per K1 block: 4 packed row-pairs
#define NCH 4             // chunks per K1 block (key-split: 1024 keys)
#define NROWS (BB * QQ)
#define CAP 256
#define TAU 2e-7f

typedef unsigned long long ull;
#define SGN2   0x8000000080000000ULL
#define ONES2  0x3F8000003F800000ULL
#define SC2    0x4380000043800000ULL   // (256.0f, 256.0f) exact 2^8 scale

static __device__ __forceinline__ ull pk2(float a, float b) {
    ull r; asm("mov.b64 %0,{%1,%2};" : "=l"(r) : "f"(a), "f"(b)); return r;
}
static __device__ __forceinline__ void upk2(ull v, float& a, float& b) {
    asm("mov.b64 {%0,%1},%2;" : "=f"(a), "=f"(b) : "l"(v));
}
static __device__ __forceinline__ ull add2(ull a, ull b) {
    ull r; asm("add.rn.f32x2 %0,%1,%2;" : "=l"(r) : "l"(a), "l"(b)); return r;
}
static __device__ __forceinline__ ull mul2(ull a, ull b) {
    ull r; asm("mul.rn.f32x2 %0,%1,%2;" : "=l"(r) : "l"(a), "l"(b)); return r;
}

// Per-(row, key-half) partial sums. Each slot is WRITTEN by exactly one K1
// block every call (no accumulation -> no zero-init kernel needed).
__device__ float g_part[NROWS * 2];

// ---------------------------------------------------------------------------
// K1: producer. Block = 8 rows x 1024 keys; grid 1024. Writes raw
// r10 = (256 p)^10 into W; writes per-(row,half) sums to g_part (plain STG).
// ---------------------------------------------------------------------------
__global__ void __launch_bounds__(256, 4) prod10_kernel(
    const float* __restrict__ qbits,
    const float* __restrict__ kbits,
    const int*   __restrict__ mask,
    float*       __restrict__ W)
{
    __shared__ float skey[CHUNK * 20];     // pad 20 -> conflict-free LDS.128
    __shared__ int   smask[CHUNK];
    __shared__ ull   sqn[4][NB];           // packed negated q bits per pair
    __shared__ float spart[4][2][2];       // [pair][h][row-in-pair]

    const int tid = threadIdx.x;
    const int w   = tid >> 5;              // warp 0..7
    const int kx  = tid & 31;
    const int p   = w >> 1;                // row-pair 0..3
    const int h   = w & 1;                 // key half within chunk
    const int bid = blockIdx.x;
    const int kh  = bid & 1;               // key half of the row
    const int qt  = (bid >> 1) & 127;
    const int b   = bid >> 8;
    const int rowbase = b * QQ + qt * ROWS;
    const int rowA = rowbase + 2 * p;
    const int rowB = rowA + 1;

    if (tid < 4 * NB) {                    // packed negated query bits
        int pp = tid >> 4, bit = tid & 15;
        int rA = rowbase + 2 * pp;
        float qa = qbits[(size_t)rA * NB + bit];
        float qc = qbits[(size_t)(rA + 1) * NB + bit];
        sqn[pp][bit] = pk2(-qa, -qc);
    }

    float* wrA = W + (size_t)rowA * KKEYS;
    float* wrB = W + (size_t)rowB * KKEYS;
    const float4* kbase4 = (const float4*)(kbits + (size_t)b * KKEYS * NB);
    const int*    mbase  = mask + b * KKEYS;

    ull s2 = 0ULL;                         // packed partial sums (rowA,rowB)
    for (int c = 0; c < NCH; c++) {
        const int cg = kh * NCH + c;       // global chunk 0..7
#pragma unroll
        for (int it = 0; it < 4; it++) {   // stage 256 keys x 16 floats
            int i = tid + it * 256;
            int k = i >> 2, j = i & 3;
            float4 v = kbase4[(size_t)(cg * CHUNK + k) * 4 + j];
            *(float4*)&skey[k * 20 + j * 4] = v;
        }
        if (tid < CHUNK) smask[tid] = mbase[cg * CHUNK + tid];
        __syncthreads();

        ull prod[4];
#pragma unroll 1
        for (int g = 0; g < 4; g++) {      // bit-group outer: few live q-regs
            const ull q0 = sqn[p][g * 4 + 0];
            const ull q1 = sqn[p][g * 4 + 1];
            const ull q2 = sqn[p][g * 4 + 2];
            const ull q3 = sqn[p][g * 4 + 3];
#pragma unroll
            for (int j = 0; j < 4; j++) {
                const int kl = h * 128 + j * 32 + kx;
                float4 kv = *(const float4*)&skey[kl * 20 + g * 4];
                // t = 1 - |q-k| = 1 + ((k-q) | signbit)
                ull t0 = add2(ONES2, add2(q0, pk2(kv.x, kv.x)) | SGN2);
                ull t1 = add2(ONES2, add2(q1, pk2(kv.y, kv.y)) | SGN2);
                ull t2 = add2(ONES2, add2(q2, pk2(kv.z, kv.z)) | SGN2);
                ull t3 = add2(ONES2, add2(q3, pk2(kv.w, kv.w)) | SGN2);
                ull m  = mul2(mul2(t0, t1), mul2(t2, t3));
                prod[j] = (g == 0) ? m : mul2(prod[j], m);
            }
        }
#pragma unroll
        for (int j = 0; j < 4; j++) {
            const int kl = h * 128 + j * 32 + kx;
            // r10 = (256*p)^10  (exact 2^80 scale; max-free normalization)
            ull r   = mul2(prod[j], SC2);
            ull r2  = mul2(r, r);
            ull r4  = mul2(r2, r2);
            ull r8  = mul2(r4, r4);
            ull r10 = mul2(r8, r2);
            float ra, rb; upk2(r10, ra, rb);
            if (smask[kl] == 0) { ra = 0.0f; rb = 0.0f; }
            const int kg = cg * CHUNK + kl;
            wrA[kg] = ra;
            wrB[kg] = rb;
            s2 = add2(s2, pk2(ra, rb));
        }
        __syncthreads();
    }

    // combine the two h-warps' partials per row in smem, then ONE plain STG
    float sA, sB; upk2(s2, sA, sB);
#pragma unroll
    for (int off = 16; off; off >>= 1) {
        sA += __shfl_xor_sync(0xffffffffu, sA, off);
        sB += __shfl_xor_sync(0xffffffffu, sB, off);
    }
    if (kx == 0) { spart[p][h][0] = sA; spart[p][h][1] = sB; }
    __syncthreads();
    if (tid < 8) {
        int pp = tid >> 1, rp = tid & 1;
        float s = spart[pp][0][rp] + spart[pp][1][rp];
        g_part[(rowbase + 2 * pp + rp) * 2 + kh] = s;
    }
}

// ---------------------------------------------------------------------------
// K2: combined consumer, one block per row (grid 4096). Uses g_part from K1 —
// NO block reduction. Chain: issue W loads -> barrier (overlapped) ->
// normalize+store+compact -> barrier -> sparse GEMV.
// ---------------------------------------------------------------------------
__global__ void __launch_bounds__(256, 8) norm_gemv_kernel(
    float*       __restrict__ W,
    const float* __restrict__ vals,
    float*       __restrict__ Out)
{
    __shared__ float sw[CAP];
    __shared__ int   sidx[CAP];
    __shared__ int   scnt;

    const int row = blockIdx.x;
    const int b   = row >> 10;
    const int tid = threadIdx.x;
    float4* wr4 = (float4*)(W + (size_t)row * KKEYS);

    if (tid == 0) scnt = 0;

    // issue loads first: W row chunks + the row sum (latency hides under barrier)
    float4 v0 = wr4[tid];
    float4 v1 = wr4[tid + 256];
    const float invs = 1.0f / (g_part[2 * row] + g_part[2 * row + 1]);
    __syncthreads();                       // scnt=0 visible

    // normalize + write back + compact (S ~ 7 -> few smem atomics)
    v0.x *= invs; v0.y *= invs; v0.z *= invs; v0.w *= invs;
    v1.x *= invs; v1.y *= invs; v1.z *= invs; v1.w *= invs;
    wr4[tid]       = v0;
    wr4[tid + 256] = v1;
    {
        float e[8] = {v0.x, v0.y, v0.z, v0.w, v1.x, v1.y, v1.z, v1.w};
#pragma unroll
        for (int q = 0; q < 8; q++) {
            if (e[q] > TAU) {
                int pos = atomicAdd(&scnt, 1);
                int k = (q < 4) ? (tid * 4 + q) : ((tid + 256) * 4 + q - 4);
                if (pos < CAP) { sw[pos] = e[q]; sidx[pos] = k; }
            }
        }
    }
    __syncthreads();

    const int S = scnt;
    const float* V = vals + (size_t)b * KKEYS * VD;
    float ax = 0.0f, ay = 0.0f;
    if (S <= CAP) {
        for (int s = 0; s < S; s++) {
            float wgt = sw[s];
            const float2 v = ((const float2*)(V + (size_t)sidx[s] * VD))[tid];
            ax = fmaf(wgt, v.x, ax);
            ay = fmaf(wgt, v.y, ay);
        }
    } else {
        // dense fallback: W row normalized above (ordered by the barrier)
        const float* wr = W + (size_t)row * KKEYS;
        for (int k = 0; k < KKEYS; k++) {
            float wgt = wr[k];
            if (wgt > TAU) {
                const float2 v = ((const float2*)(V + (size_t)k * VD))[tid];
                ax = fmaf(wgt, v.x, ax);
                ay = fmaf(wgt, v.y, ay);
            }
        }
    }
    ((float2*)(Out + (size_t)row * VD))[tid] = make_float2(ax, ay);
}

// ---------------------------------------------------------------------------
// Launch: out layout = [output (B,Q,V) | weights (B,Q,K)] per reference tuple.
// ---------------------------------------------------------------------------
extern "C" void kernel_launch(void* const* d_in, const int* in_sizes, int n_in,
                              void* d_out, int out_size)
{
    (void)in_sizes; (void)n_in; (void)out_size;
    const float* qb   = (const float*)d_in[0];
    const float* kb   = (const float*)d_in[1];
    const float* vals = (const float*)d_in[2];
    const int*   mask = (const int*)d_in[3];

    float* out = (float*)d_out;
    float* W   = out + (size_t)BB * QQ * VD;   // weights region

    prod10_kernel<<<BB * (QQ / ROWS) * 2, 256>>>(qb, kb, mask, W);
    norm_gemv_kernel<<<NROWS, 256>>>(W, vals, out);
}